// round 3
// baseline (speedup 1.0000x reference)
#include <cuda_runtime.h>

#define TT 1024
#define NTHR 128
#define NBLK 512

struct Q { float w, x, y, z; };
struct V3 { float x, y, z; };

__device__ __forceinline__ Q qmul(const Q a, const Q b) {
    return Q{ a.w*b.w - a.x*b.x - a.y*b.y - a.z*b.z,
              a.w*b.x + a.x*b.w + a.y*b.z - a.z*b.y,
              a.w*b.y - a.x*b.z + a.y*b.w + a.z*b.x,
              a.w*b.z + a.x*b.y - a.y*b.x + a.z*b.w };
}
__device__ __forceinline__ Q qconj(const Q q) { return Q{q.w, -q.x, -q.y, -q.z}; }

__device__ __forceinline__ V3 qrot(const Q q, const V3 v) {
    float tx = 2.0f*(q.y*v.z - q.z*v.y);
    float ty = 2.0f*(q.z*v.x - q.x*v.z);
    float tz = 2.0f*(q.x*v.y - q.y*v.x);
    return V3{ v.x + q.w*tx + (q.y*tz - q.z*ty),
               v.y + q.w*ty + (q.z*tx - q.x*tz),
               v.z + q.w*tz + (q.x*ty - q.y*tx) };
}

// ||R(a)-R(b)||_F^2 = 8*(1 - dot(a,b)^2) for unit quats
__device__ __forceinline__ float qdot(const Q a, const Q b) {
    return fmaf(a.w, b.w, fmaf(a.x, b.x, fmaf(a.y, b.y, a.z*b.z)));
}

__device__ __forceinline__ float n2(const V3 a) {
    return fmaf(a.x, a.x, fmaf(a.y, a.y, a.z*a.z));
}

__device__ __forceinline__ Q loadnq(const float* __restrict__ p, int src_c,
                                    const float* __restrict__ mn, const float* __restrict__ sd, int mc) {
    float w = fmaf(p[(src_c+0)*TT], sd[mc+0], mn[mc+0]);
    float x = fmaf(p[(src_c+1)*TT], sd[mc+1], mn[mc+1]);
    float y = fmaf(p[(src_c+2)*TT], sd[mc+2], mn[mc+2]);
    float z = fmaf(p[(src_c+3)*TT], sd[mc+3], mn[mc+3]);
    float inv = rsqrtf(fmaf(w, w, fmaf(x, x, fmaf(y, y, z*z))));
    return Q{w*inv, x*inv, y*inv, z*inv};
}

__device__ float g_part[NBLK];
__device__ unsigned int g_ctr = 0;

__global__ void __launch_bounds__(NTHR, 8) fk_loss_kernel(
    const float* __restrict__ ik,   // (64, 168, 1024)
    const float* __restrict__ dec,  // (64, 176, 1024)
    const float* __restrict__ tgt,  // (64, 176, 1024)
    const float* __restrict__ mean, // (176,)
    const float* __restrict__ stdv, // (176,)
    const float* __restrict__ offs, // (22, 3)
    float* __restrict__ out)
{
    __shared__ float smn[176], ssd[176], soff[66];
    for (int i = threadIdx.x; i < 176; i += NTHR) { smn[i] = mean[i]; ssd[i] = stdv[i]; }
    for (int i = threadIdx.x; i < 66; i += NTHR) soff[i] = offs[i];
    __syncthreads();

    int tid = blockIdx.x * NTHR + threadIdx.x;
    int b = tid >> 10, t = tid & 1023;
    const float* ikp = ik  + (size_t)b * 168 * TT + t;
    const float* dcp = dec + (size_t)b * 176 * TT + t;
    const float* tgp = tgt + (size_t)b * 176 * TT + t;

    // target root quat (ik/dec roots are identity; tgt local-root forced to identity too,
    // so global tgt rot telescopes to conj(qr0)*qr_j)
    Q qc0 = qconj(loadnq(tgp, 0, smn, ssd, 0));

    // chain state (static indices only -> registers / minimal spills)
    Q  gI[22], gD[22], gT[22];
    V3 dDI[22], dIT[22];   // pD - pI, pI - pT

    float aep = 0.0f, aer = 0.0f, anp = 0.0f, anr = 0.0f;

    // NS joint: advance all three chains; loss dec-vs-ik (pos diff + rot dot)
#define STEP_NS(j, p) do {                                                     \
    Q qi = loadnq(ikp, ((j)-1)*8, smn, ssd, (j)*8);                            \
    Q qd = loadnq(dcp, (j)*8,     smn, ssd, (j)*8);                            \
    Q qt = loadnq(tgp, (j)*8,     smn, ssd, (j)*8);                            \
    gI[j] = qi; gD[j] = qd; gT[j] = qmul(qc0, qt);                             \
    if ((p) == 0) {                                                            \
        dDI[j] = V3{0.f,0.f,0.f}; dIT[j] = V3{0.f,0.f,0.f};                    \
    } else {                                                                   \
        V3 off = V3{soff[3*(j)], soff[3*(j)+1], soff[3*(j)+2]};                \
        V3 rI = qrot(gI[p], off);                                              \
        V3 rD = qrot(gD[p], off);                                              \
        V3 rT = qrot(gT[p], off);                                              \
        dDI[j] = V3{dDI[p].x + rD.x - rI.x, dDI[p].y + rD.y - rI.y,            \
                    dDI[p].z + rD.z - rI.z};                                   \
        dIT[j] = V3{dIT[p].x + rI.x - rT.x, dIT[p].y + rI.y - rT.y,            \
                    dIT[p].z + rI.z - rT.z};                                   \
    }                                                                          \
    anp += n2(dDI[j]);                                                         \
    { float d = qdot(qd, qi); anr += fmaf(-d, d, 1.0f); }                      \
} while (0)

    // EE joint (leaf): dec chain skipped; loss ik-vs-tgt
#define STEP_EE(j, p) do {                                                     \
    Q qi = loadnq(ikp, ((j)-1)*8, smn, ssd, (j)*8);                            \
    Q qt = loadnq(tgp, (j)*8,     smn, ssd, (j)*8);                            \
    Q gt = qmul(qc0, qt);                                                      \
    V3 off = V3{soff[3*(j)], soff[3*(j)+1], soff[3*(j)+2]};                    \
    V3 rI = qrot(gI[p], off);                                                  \
    V3 rT = qrot(gT[p], off);                                                  \
    V3 d = V3{dIT[p].x + rI.x - rT.x, dIT[p].y + rI.y - rT.y,                  \
              dIT[p].z + rI.z - rT.z};                                         \
    aep += n2(d);                                                              \
    { float dd = qdot(qi, gt); aer += fmaf(-dd, dd, 1.0f); }                   \
} while (0)

    STEP_NS(1, 0);  STEP_NS(2, 1);  STEP_NS(3, 2);   STEP_EE(4, 3);
    STEP_NS(5, 0);  STEP_NS(6, 5);  STEP_NS(7, 6);   STEP_EE(8, 7);
    STEP_NS(9, 0);  STEP_NS(10, 9); STEP_NS(11, 10);
    STEP_NS(12, 11); STEP_EE(13, 12);
    STEP_NS(14, 11); STEP_NS(15, 14); STEP_NS(16, 15); STEP_EE(17, 16);
    STEP_NS(18, 11); STEP_NS(19, 18); STEP_NS(20, 19); STEP_EE(21, 20);

#undef STEP_NS
#undef STEP_EE

    const float NBT = 65536.0f;
    float s = aep * (1.0f / (NBT * 15.0f))
            + aer * (8.0f / (NBT * 45.0f))
            + anp * (0.1f / (NBT * 48.0f))
            + anr * (0.8f / (NBT * 144.0f));

    // block reduction -> deterministic per-block partial
#pragma unroll
    for (int o = 16; o; o >>= 1) s += __shfl_down_sync(0xffffffffu, s, o);
    __shared__ float ws[NTHR / 32];
    __shared__ bool is_last;
    if ((threadIdx.x & 31) == 0) ws[threadIdx.x >> 5] = s;
    __syncthreads();
    if (threadIdx.x == 0) {
        float v = 0.0f;
#pragma unroll
        for (int i = 0; i < NTHR / 32; i++) v += ws[i];
        g_part[blockIdx.x] = v;
        __threadfence();
        unsigned int old = atomicAdd(&g_ctr, 1u);
        is_last = (old == NBLK - 1);
    }
    __syncthreads();

    // last-arriving block: deterministic final reduction of 512 partials
    if (is_last && threadIdx.x < 32) {
        volatile float* vp = g_part;
        float v = 0.0f;
#pragma unroll
        for (int i = 0; i < NBLK / 32; i++) v += vp[threadIdx.x + i * 32];
#pragma unroll
        for (int o = 16; o; o >>= 1) v += __shfl_down_sync(0xffffffffu, v, o);
        if (threadIdx.x == 0) {
            out[0] = v;
            g_ctr = 0;   // reset for next graph replay
        }
    }
}

extern "C" void kernel_launch(void* const* d_in, const int* in_sizes, int n_in,
                              void* d_out, int out_size) {
    // metadata order: input(unused), input_ik, input_decoder, target, mean_dqs, std_dqs, offsets
    const float* ik   = (const float*)d_in[1];
    const float* dec  = (const float*)d_in[2];
    const float* tgt  = (const float*)d_in[3];
    const float* mean = (const float*)d_in[4];
    const float* stdv = (const float*)d_in[5];
    const float* offs = (const float*)d_in[6];
    float* out = (float*)d_out;

    fk_loss_kernel<<<NBLK, NTHR>>>(ik, dec, tgt, mean, stdv, offs, out);
}

// round 5
// speedup vs baseline: 1.0086x; 1.0086x over previous
#include <cuda_runtime.h>

#define TT 1024
#define NTHR 128
#define NBLK 2048   // 4 roles x 512 blocks

struct Q { float w, x, y, z; };
struct V3 { float x, y, z; };
struct St { Q gI, gD, gT; V3 dDI, dIT; };

__device__ __forceinline__ Q qmul(const Q a, const Q b) {
    return Q{ a.w*b.w - a.x*b.x - a.y*b.y - a.z*b.z,
              a.w*b.x + a.x*b.w + a.y*b.z - a.z*b.y,
              a.w*b.y - a.x*b.z + a.y*b.w + a.z*b.x,
              a.w*b.z + a.x*b.y - a.y*b.x + a.z*b.w };
}
__device__ __forceinline__ Q qconj(const Q q) { return Q{q.w, -q.x, -q.y, -q.z}; }

__device__ __forceinline__ V3 qrot(const Q q, const V3 v) {
    float tx = 2.0f*(q.y*v.z - q.z*v.y);
    float ty = 2.0f*(q.z*v.x - q.x*v.z);
    float tz = 2.0f*(q.x*v.y - q.y*v.x);
    return V3{ v.x + q.w*tx + (q.y*tz - q.z*ty),
               v.y + q.w*ty + (q.z*tx - q.x*tz),
               v.z + q.w*tz + (q.x*ty - q.y*tx) };
}

// ||R(a)-R(b)||_F^2 = 8*(1 - dot(a,b)^2) for unit quats
__device__ __forceinline__ float qdot(const Q a, const Q b) {
    return fmaf(a.w, b.w, fmaf(a.x, b.x, fmaf(a.y, b.y, a.z*b.z)));
}
__device__ __forceinline__ float n2(const V3 a) {
    return fmaf(a.x, a.x, fmaf(a.y, a.y, a.z*a.z));
}

__device__ __forceinline__ Q loadnq(const float* __restrict__ p, int src_c,
                                    const float* __restrict__ mn, const float* __restrict__ sd, int mc) {
    float w = fmaf(p[(src_c+0)*TT], sd[mc+0], mn[mc+0]);
    float x = fmaf(p[(src_c+1)*TT], sd[mc+1], mn[mc+1]);
    float y = fmaf(p[(src_c+2)*TT], sd[mc+2], mn[mc+2]);
    float z = fmaf(p[(src_c+3)*TT], sd[mc+3], mn[mc+3]);
    float inv = rsqrtf(fmaf(w, w, fmaf(x, x, fmaf(y, y, z*z))));
    return Q{w*inv, x*inv, y*inv, z*inv};
}

__device__ float g_part[NBLK];
__device__ unsigned int g_ctr = 0;

struct Ctx {
    const float *ikp, *dcp, *tgp;
    const float *smn, *ssd, *soff;
    Q qc0;
    float anp, anr, aep, aer;
};

// TELESCOPED globals: rots[j] = conj(qr0)*qr_j. For ik/dec, qr0 = identity,
// so the global rotation at joint j is just the normalized joint quat.

// NS root child (parent = 0): position diffs are zero
__device__ __forceinline__ St step_root(Ctx& c, int j, bool acc) {
    Q qi = loadnq(c.ikp, (j-1)*8, c.smn, c.ssd, j*8);
    Q qd = loadnq(c.dcp, j*8,     c.smn, c.ssd, j*8);
    Q qt = loadnq(c.tgp, j*8,     c.smn, c.ssd, j*8);
    if (acc) { float d = qdot(qd, qi); c.anr += fmaf(-d, d, 1.0f); }
    return St{qi, qd, qmul(c.qc0, qt), V3{0,0,0}, V3{0,0,0}};
}

// NS interior joint: globals are the (telescoped) joint quats, NOT chained
__device__ __forceinline__ St step_ns(Ctx& c, const St& sp, int j, bool acc) {
    Q qi = loadnq(c.ikp, (j-1)*8, c.smn, c.ssd, j*8);
    Q qd = loadnq(c.dcp, j*8,     c.smn, c.ssd, j*8);
    Q qt = loadnq(c.tgp, j*8,     c.smn, c.ssd, j*8);
    V3 off = V3{c.soff[3*j], c.soff[3*j+1], c.soff[3*j+2]};
    V3 rI = qrot(sp.gI, off);
    V3 rD = qrot(sp.gD, off);
    V3 rT = qrot(sp.gT, off);
    St s;
    s.gI = qi;
    s.gD = qd;
    s.gT = qmul(c.qc0, qt);
    s.dDI = V3{sp.dDI.x + rD.x - rI.x, sp.dDI.y + rD.y - rI.y, sp.dDI.z + rD.z - rI.z};
    s.dIT = V3{sp.dIT.x + rI.x - rT.x, sp.dIT.y + rI.y - rT.y, sp.dIT.z + rI.z - rT.z};
    if (acc) {
        c.anp += n2(s.dDI);
        float d = qdot(qd, qi); c.anr += fmaf(-d, d, 1.0f);
    }
    return s;
}

// EE leaf: ik-vs-tgt loss only, dec chain not needed
__device__ __forceinline__ void step_ee(Ctx& c, const St& sp, int j) {
    Q qi = loadnq(c.ikp, (j-1)*8, c.smn, c.ssd, j*8);
    Q qt = loadnq(c.tgp, j*8,     c.smn, c.ssd, j*8);
    Q gt = qmul(c.qc0, qt);
    V3 off = V3{c.soff[3*j], c.soff[3*j+1], c.soff[3*j+2]};
    V3 rI = qrot(sp.gI, off);
    V3 rT = qrot(sp.gT, off);
    V3 d = V3{sp.dIT.x + rI.x - rT.x, sp.dIT.y + rI.y - rT.y, sp.dIT.z + rI.z - rT.z};
    c.aep += n2(d);
    float dd = qdot(qi, gt); c.aer += fmaf(-dd, dd, 1.0f);
}

__global__ void __launch_bounds__(NTHR) fk_loss_kernel(
    const float* __restrict__ ik,   // (64, 168, 1024)
    const float* __restrict__ dec,  // (64, 176, 1024)
    const float* __restrict__ tgt,  // (64, 176, 1024)
    const float* __restrict__ mean, // (176,)
    const float* __restrict__ stdv, // (176,)
    const float* __restrict__ offs, // (22, 3)
    float* __restrict__ out)
{
    __shared__ float smn[176], ssd[176], soff[66];
    for (int i = threadIdx.x; i < 176; i += NTHR) { smn[i] = mean[i]; ssd[i] = stdv[i]; }
    for (int i = threadIdx.x; i < 66; i += NTHR) soff[i] = offs[i];
    __syncthreads();

    int role  = blockIdx.x >> 9;                         // 0..3
    int inner = ((blockIdx.x & 511) << 7) | threadIdx.x; // 0..65535
    int b = inner >> 10, t = inner & 1023;

    Ctx c;
    c.ikp = ik  + (size_t)b * 168 * TT + t;
    c.dcp = dec + (size_t)b * 176 * TT + t;
    c.tgp = tgt + (size_t)b * 176 * TT + t;
    c.smn = smn; c.ssd = ssd; c.soff = soff;
    c.anp = 0.0f; c.anr = 0.0f; c.aep = 0.0f; c.aer = 0.0f;

    // target root quat
    c.qc0 = qconj(loadnq(c.tgp, 0, smn, ssd, 0));

    if (role == 0) {
        // arm chains A (1-4) and B (5-8)
        St s1 = step_root(c, 1, true);
        St s2 = step_ns(c, s1, 2, true);
        St s3 = step_ns(c, s2, 3, true);
        step_ee(c, s3, 4);
        St s5 = step_root(c, 5, true);
        St s6 = step_ns(c, s5, 6, true);
        St s7 = step_ns(c, s6, 7, true);
        step_ee(c, s7, 8);
    } else {
        // spine 9-11 (loss terms owned by role 1 only)
        bool acc = (role == 1);
        St s9  = step_root(c, 9, acc);
        St s10 = step_ns(c, s9, 10, acc);
        St s11 = step_ns(c, s10, 11, acc);
        if (role == 1) {
            St s12 = step_ns(c, s11, 12, true);
            step_ee(c, s12, 13);
        } else if (role == 2) {
            St s14 = step_ns(c, s11, 14, true);
            St s15 = step_ns(c, s14, 15, true);
            St s16 = step_ns(c, s15, 16, true);
            step_ee(c, s16, 17);
        } else {
            St s18 = step_ns(c, s11, 18, true);
            St s19 = step_ns(c, s18, 19, true);
            St s20 = step_ns(c, s19, 20, true);
            step_ee(c, s20, 21);
        }
    }

    const float NBT = 65536.0f;
    float s = c.aep * (1.0f / (NBT * 15.0f))
            + c.aer * (8.0f / (NBT * 45.0f))
            + c.anp * (0.1f / (NBT * 48.0f))
            + c.anr * (0.8f / (NBT * 144.0f));

    // block reduction -> deterministic per-block partial
#pragma unroll
    for (int o = 16; o; o >>= 1) s += __shfl_down_sync(0xffffffffu, s, o);
    __shared__ float ws[NTHR / 32];
    __shared__ bool is_last;
    if ((threadIdx.x & 31) == 0) ws[threadIdx.x >> 5] = s;
    __syncthreads();
    if (threadIdx.x == 0) {
        float v = 0.0f;
#pragma unroll
        for (int i = 0; i < NTHR / 32; i++) v += ws[i];
        g_part[blockIdx.x] = v;
        __threadfence();
        unsigned int old = atomicAdd(&g_ctr, 1u);
        is_last = (old == NBLK - 1);
    }
    __syncthreads();

    // last-arriving block: deterministic final reduction of all partials
    if (is_last && threadIdx.x < 32) {
        volatile float* vp = g_part;
        float v = 0.0f;
#pragma unroll
        for (int i = 0; i < NBLK / 32; i++) v += vp[threadIdx.x + i * 32];
#pragma unroll
        for (int o = 16; o; o >>= 1) v += __shfl_down_sync(0xffffffffu, v, o);
        if (threadIdx.x == 0) {
            out[0] = v;
            g_ctr = 0;   // reset for next graph replay
        }
    }
}

extern "C" void kernel_launch(void* const* d_in, const int* in_sizes, int n_in,
                              void* d_out, int out_size) {
    // metadata order: input(unused), input_ik, input_decoder, target, mean_dqs, std_dqs, offsets
    const float* ik   = (const float*)d_in[1];
    const float* dec  = (const float*)d_in[2];
    const float* tgt  = (const float*)d_in[3];
    const float* mean = (const float*)d_in[4];
    const float* stdv = (const float*)d_in[5];
    const float* offs = (const float*)d_in[6];
    float* out = (float*)d_out;

    fk_loss_kernel<<<NBLK, NTHR>>>(ik, dec, tgt, mean, stdv, offs, out);
}

// round 7
// speedup vs baseline: 1.0735x; 1.0643x over previous
#include <cuda_runtime.h>

#define TT 1024
#define NTHR 64
#define NBLK 1024

struct Q { float w, x, y, z; };
struct V3 { float x, y, z; };

__device__ __forceinline__ Q qmul(const Q a, const Q b) {
    return Q{ a.w*b.w - a.x*b.x - a.y*b.y - a.z*b.z,
              a.w*b.x + a.x*b.w + a.y*b.z - a.z*b.y,
              a.w*b.y - a.x*b.z + a.y*b.w + a.z*b.x,
              a.w*b.z + a.x*b.y - a.y*b.x + a.z*b.w };
}
__device__ __forceinline__ Q qconj(const Q q) { return Q{q.w, -q.x, -q.y, -q.z}; }

__device__ __forceinline__ V3 qrot(const Q q, const V3 v) {
    float tx = 2.0f*(q.y*v.z - q.z*v.y);
    float ty = 2.0f*(q.z*v.x - q.x*v.z);
    float tz = 2.0f*(q.x*v.y - q.y*v.x);
    return V3{ v.x + q.w*tx + (q.y*tz - q.z*ty),
               v.y + q.w*ty + (q.z*tx - q.x*tz),
               v.z + q.w*tz + (q.x*ty - q.y*tx) };
}

// ||R(a)-R(b)||_F^2 = 8*(1 - dot(a,b)^2) for unit quats
__device__ __forceinline__ float qdot(const Q a, const Q b) {
    return fmaf(a.w, b.w, fmaf(a.x, b.x, fmaf(a.y, b.y, a.z*b.z)));
}
__device__ __forceinline__ float n2(const V3 a) {
    return fmaf(a.x, a.x, fmaf(a.y, a.y, a.z*a.z));
}

// streaming global load (single-use data, evict-first)
__device__ __forceinline__ float ldg_cs(const float* p) { return __ldcs(p); }

__device__ __forceinline__ Q loadnq(const float* __restrict__ p, int src_c,
                                    const float* __restrict__ mn, const float* __restrict__ sd, int mc) {
    float w = fmaf(ldg_cs(p + (src_c+0)*TT), sd[mc+0], mn[mc+0]);
    float x = fmaf(ldg_cs(p + (src_c+1)*TT), sd[mc+1], mn[mc+1]);
    float y = fmaf(ldg_cs(p + (src_c+2)*TT), sd[mc+2], mn[mc+2]);
    float z = fmaf(ldg_cs(p + (src_c+3)*TT), sd[mc+3], mn[mc+3]);
    float inv = rsqrtf(fmaf(w, w, fmaf(x, x, fmaf(y, y, z*z))));
    return Q{w*inv, x*inv, y*inv, z*inv};
}

__device__ float g_part[NBLK];
__device__ unsigned int g_ctr = 0;

__global__ void __launch_bounds__(NTHR) fk_loss_kernel(
    const float* __restrict__ ik,   // (64, 168, 1024)
    const float* __restrict__ dec,  // (64, 176, 1024)
    const float* __restrict__ tgt,  // (64, 176, 1024)
    const float* __restrict__ mean, // (176,)
    const float* __restrict__ stdv, // (176,)
    const float* __restrict__ offs, // (22, 3)
    float* __restrict__ out)
{
    __shared__ float smn[176], ssd[176], soff[66];
    for (int i = threadIdx.x; i < 176; i += NTHR) { smn[i] = mean[i]; ssd[i] = stdv[i]; }
    for (int i = threadIdx.x; i < 66; i += NTHR) soff[i] = offs[i];
    __syncthreads();

    int tid = blockIdx.x * NTHR + threadIdx.x;
    int b = tid >> 10, t = tid & 1023;
    const float* ikp = ik  + (size_t)b * 168 * TT + t;
    const float* dcp = dec + (size_t)b * 176 * TT + t;
    const float* tgp = tgt + (size_t)b * 176 * TT + t;

    // target root quat (ik/dec roots are identity; globals telescope: rots[j]=conj(qr0)*qr_j)
    Q qc0 = qconj(loadnq(tgp, 0, smn, ssd, 0));

    Q  gI[22], gT[22];
    V3 dDI[22], dIT[22];   // pD - pI, pI - pT
    Q  gD[22];

    float aep = 0.0f, aer = 0.0f, anp = 0.0f, anr = 0.0f;

#define STEP_NS(j, p) do {                                                     \
    Q qi = loadnq(ikp, ((j)-1)*8, smn, ssd, (j)*8);                            \
    Q qd = loadnq(dcp, (j)*8,     smn, ssd, (j)*8);                            \
    Q qt = loadnq(tgp, (j)*8,     smn, ssd, (j)*8);                            \
    gI[j] = qi; gD[j] = qd; gT[j] = qmul(qc0, qt);                             \
    if ((p) == 0) {                                                            \
        dDI[j] = V3{0.f,0.f,0.f}; dIT[j] = V3{0.f,0.f,0.f};                    \
    } else {                                                                   \
        V3 off = V3{soff[3*(j)], soff[3*(j)+1], soff[3*(j)+2]};                \
        V3 rI = qrot(gI[p], off);                                              \
        V3 rD = qrot(gD[p], off);                                              \
        V3 rT = qrot(gT[p], off);                                              \
        dDI[j] = V3{dDI[p].x + rD.x - rI.x, dDI[p].y + rD.y - rI.y,            \
                    dDI[p].z + rD.z - rI.z};                                   \
        dIT[j] = V3{dIT[p].x + rI.x - rT.x, dIT[p].y + rI.y - rT.y,            \
                    dIT[p].z + rI.z - rT.z};                                   \
    }                                                                          \
    anp += n2(dDI[j]);                                                         \
    { float d = qdot(qd, qi); anr += fmaf(-d, d, 1.0f); }                      \
} while (0)

#define STEP_EE(j, p) do {                                                     \
    Q qi = loadnq(ikp, ((j)-1)*8, smn, ssd, (j)*8);                            \
    Q qt = loadnq(tgp, (j)*8,     smn, ssd, (j)*8);                            \
    Q gt = qmul(qc0, qt);                                                      \
    V3 off = V3{soff[3*(j)], soff[3*(j)+1], soff[3*(j)+2]};                    \
    V3 rI = qrot(gI[p], off);                                                  \
    V3 rT = qrot(gT[p], off);                                                  \
    V3 d = V3{dIT[p].x + rI.x - rT.x, dIT[p].y + rI.y - rT.y,                  \
              dIT[p].z + rI.z - rT.z};                                         \
    aep += n2(d);                                                              \
    { float dd = qdot(qi, gt); aer += fmaf(-dd, dd, 1.0f); }                   \
} while (0)

    STEP_NS(1, 0);  STEP_NS(2, 1);  STEP_NS(3, 2);   STEP_EE(4, 3);
    STEP_NS(5, 0);  STEP_NS(6, 5);  STEP_NS(7, 6);   STEP_EE(8, 7);
    STEP_NS(9, 0);  STEP_NS(10, 9); STEP_NS(11, 10);
    STEP_NS(12, 11); STEP_EE(13, 12);
    STEP_NS(14, 11); STEP_NS(15, 14); STEP_NS(16, 15); STEP_EE(17, 16);
    STEP_NS(18, 11); STEP_NS(19, 18); STEP_NS(20, 19); STEP_EE(21, 20);

#undef STEP_NS
#undef STEP_EE

    const float NBT = 65536.0f;
    float s = aep * (1.0f / (NBT * 15.0f))
            + aer * (8.0f / (NBT * 45.0f))
            + anp * (0.1f / (NBT * 48.0f))
            + anr * (0.8f / (NBT * 144.0f));

    // block reduction (2 warps) -> deterministic per-block partial
#pragma unroll
    for (int o = 16; o; o >>= 1) s += __shfl_down_sync(0xffffffffu, s, o);
    __shared__ float ws[NTHR / 32];
    __shared__ bool is_last;
    if ((threadIdx.x & 31) == 0) ws[threadIdx.x >> 5] = s;
    __syncthreads();
    if (threadIdx.x == 0) {
        float v = 0.0f;
#pragma unroll
        for (int i = 0; i < NTHR / 32; i++) v += ws[i];
        g_part[blockIdx.x] = v;
        __threadfence();
        unsigned int old = atomicAdd(&g_ctr, 1u);
        is_last = (old == NBLK - 1);
    }
    __syncthreads();

    // last-arriving block: deterministic final reduction of 1024 partials
    if (is_last && threadIdx.x < 32) {
        volatile float* vp = g_part;
        float v = 0.0f;
#pragma unroll
        for (int i = 0; i < NBLK / 32; i++) v += vp[threadIdx.x + i * 32];
#pragma unroll
        for (int o = 16; o; o >>= 1) v += __shfl_down_sync(0xffffffffu, v, o);
        if (threadIdx.x == 0) {
            out[0] = v;
            g_ctr = 0;   // reset for next graph replay
        }
    }
}

extern "C" void kernel_launch(void* const* d_in, const int* in_sizes, int n_in,
                              void* d_out, int out_size) {
    // metadata order: input(unused), input_ik, input_decoder, target, mean_dqs, std_dqs, offsets
    const float* ik   = (const float*)d_in[1];
    const float* dec  = (const float*)d_in[2];
    const float* tgt  = (const float*)d_in[3];
    const float* mean = (const float*)d_in[4];
    const float* stdv = (const float*)d_in[5];
    const float* offs = (const float*)d_in[6];
    float* out = (float*)d_out;

    fk_loss_kernel<<<NBLK, NTHR>>>(ik, dec, tgt, mean, stdv, offs, out);
}

// round 8
// speedup vs baseline: 1.1061x; 1.0303x over previous
#include <cuda_runtime.h>

#define TT 1024
#define NBLK 256
#define NTHR 256

struct Q { float w, x, y, z; };
struct V3 { float x, y, z; };

__device__ __forceinline__ Q qmul(const Q a, const Q b) {
    return Q{ a.w*b.w - a.x*b.x - a.y*b.y - a.z*b.z,
              a.w*b.x + a.x*b.w + a.y*b.z - a.z*b.y,
              a.w*b.y - a.x*b.z + a.y*b.w + a.z*b.x,
              a.w*b.z + a.x*b.y - a.y*b.x + a.z*b.w };
}
__device__ __forceinline__ Q qconj(const Q q) { return Q{q.w, -q.x, -q.y, -q.z}; }

__device__ __forceinline__ V3 qrot(const Q q, const V3 v) {
    float tx = 2.0f*(q.y*v.z - q.z*v.y);
    float ty = 2.0f*(q.z*v.x - q.x*v.z);
    float tz = 2.0f*(q.x*v.y - q.y*v.x);
    return V3{ v.x + q.w*tx + (q.y*tz - q.z*ty),
               v.y + q.w*ty + (q.z*tx - q.x*tz),
               v.z + q.w*tz + (q.x*ty - q.y*tx) };
}

// ||R(a)-R(b)||_F^2 = 8*(1 - dot(a,b)^2) for unit quats
__device__ __forceinline__ float qdot(const Q a, const Q b) {
    return fmaf(a.w, b.w, fmaf(a.x, b.x, fmaf(a.y, b.y, a.z*b.z)));
}
__device__ __forceinline__ float n2(const V3 a) {
    return fmaf(a.x, a.x, fmaf(a.y, a.y, a.z*a.z));
}

__device__ __forceinline__ Q loadnq(const float* __restrict__ p, int src_c,
                                    const float* __restrict__ mn, const float* __restrict__ sd, int mc) {
    float w = fmaf(p[(src_c+0)*TT], sd[mc+0], mn[mc+0]);
    float x = fmaf(p[(src_c+1)*TT], sd[mc+1], mn[mc+1]);
    float y = fmaf(p[(src_c+2)*TT], sd[mc+2], mn[mc+2]);
    float z = fmaf(p[(src_c+3)*TT], sd[mc+3], mn[mc+3]);
    float inv = rsqrtf(fmaf(w, w, fmaf(x, x, fmaf(y, y, z*z))));
    return Q{w*inv, x*inv, y*inv, z*inv};
}

__device__ float g_part[NBLK];
__device__ unsigned int g_ctr = 0;

__global__ void __launch_bounds__(NTHR, 3) fk_loss_kernel(
    const float* __restrict__ ik,   // (64, 168, 1024)
    const float* __restrict__ dec,  // (64, 176, 1024)
    const float* __restrict__ tgt,  // (64, 176, 1024)
    const float* __restrict__ mean, // (176,)
    const float* __restrict__ stdv, // (176,)
    const float* __restrict__ offs, // (22, 3)
    float* __restrict__ out)
{
    __shared__ float smn[176], ssd[176], soff[66];
    for (int i = threadIdx.x; i < 176; i += NTHR) { smn[i] = mean[i]; ssd[i] = stdv[i]; }
    for (int i = threadIdx.x; i < 66; i += NTHR) soff[i] = offs[i];
    __syncthreads();

    int tid = blockIdx.x * NTHR + threadIdx.x;
    int b = tid >> 10, t = tid & 1023;
    const float* ikp = ik  + (size_t)b * 168 * TT + t;
    const float* dcp = dec + (size_t)b * 176 * TT + t;
    const float* tgp = tgt + (size_t)b * 176 * TT + t;

    // target root quat (ik/dec roots are identity; globals telescope: rots[j]=conj(qr0)*qr_j)
    Q qc0 = qconj(loadnq(tgp, 0, smn, ssd, 0));

    Q  gI[22], gD[22], gT[22];
    V3 dDI[22], dIT[22];   // pD - pI, pI - pT

    float aep = 0.0f, aer = 0.0f, anp = 0.0f, anr = 0.0f;

#define STEP_NS(j, p) do {                                                     \
    Q qi = loadnq(ikp, ((j)-1)*8, smn, ssd, (j)*8);                            \
    Q qd = loadnq(dcp, (j)*8,     smn, ssd, (j)*8);                            \
    Q qt = loadnq(tgp, (j)*8,     smn, ssd, (j)*8);                            \
    gI[j] = qi; gD[j] = qd; gT[j] = qmul(qc0, qt);                             \
    if ((p) == 0) {                                                            \
        dDI[j] = V3{0.f,0.f,0.f}; dIT[j] = V3{0.f,0.f,0.f};                    \
    } else {                                                                   \
        V3 off = V3{soff[3*(j)], soff[3*(j)+1], soff[3*(j)+2]};                \
        V3 rI = qrot(gI[p], off);                                              \
        V3 rD = qrot(gD[p], off);                                              \
        V3 rT = qrot(gT[p], off);                                              \
        dDI[j] = V3{dDI[p].x + rD.x - rI.x, dDI[p].y + rD.y - rI.y,            \
                    dDI[p].z + rD.z - rI.z};                                   \
        dIT[j] = V3{dIT[p].x + rI.x - rT.x, dIT[p].y + rI.y - rT.y,            \
                    dIT[p].z + rI.z - rT.z};                                   \
        anp += n2(dDI[j]);                                                     \
    }                                                                          \
    { float d = qdot(qd, qi); anr += fmaf(-d, d, 1.0f); }                      \
} while (0)

#define STEP_EE(j, p) do {                                                     \
    Q qi = loadnq(ikp, ((j)-1)*8, smn, ssd, (j)*8);                            \
    Q qt = loadnq(tgp, (j)*8,     smn, ssd, (j)*8);                            \
    Q gt = qmul(qc0, qt);                                                      \
    V3 off = V3{soff[3*(j)], soff[3*(j)+1], soff[3*(j)+2]};                    \
    V3 rI = qrot(gI[p], off);                                                  \
    V3 rT = qrot(gT[p], off);                                                  \
    V3 d = V3{dIT[p].x + rI.x - rT.x, dIT[p].y + rI.y - rT.y,                  \
              dIT[p].z + rI.z - rT.z};                                         \
    aep += n2(d);                                                              \
    { float dd = qdot(qi, gt); aer += fmaf(-dd, dd, 1.0f); }                   \
} while (0)

    STEP_NS(1, 0);  STEP_NS(2, 1);  STEP_NS(3, 2);   STEP_EE(4, 3);
    STEP_NS(5, 0);  STEP_NS(6, 5);  STEP_NS(7, 6);   STEP_EE(8, 7);
    STEP_NS(9, 0);  STEP_NS(10, 9); STEP_NS(11, 10);
    STEP_NS(12, 11); STEP_EE(13, 12);
    STEP_NS(14, 11); STEP_NS(15, 14); STEP_NS(16, 15); STEP_EE(17, 16);
    STEP_NS(18, 11); STEP_NS(19, 18); STEP_NS(20, 19); STEP_EE(21, 20);

#undef STEP_NS
#undef STEP_EE

    const float NBT = 65536.0f;
    float s = aep * (1.0f / (NBT * 15.0f))
            + aer * (8.0f / (NBT * 45.0f))
            + anp * (0.1f / (NBT * 48.0f))
            + anr * (0.8f / (NBT * 144.0f));

    // block reduction -> deterministic per-block partial
#pragma unroll
    for (int o = 16; o; o >>= 1) s += __shfl_down_sync(0xffffffffu, s, o);
    __shared__ float ws[NTHR / 32];
    __shared__ bool is_last;
    if ((threadIdx.x & 31) == 0) ws[threadIdx.x >> 5] = s;
    __syncthreads();
    if (threadIdx.x == 0) {
        float v = 0.0f;
#pragma unroll
        for (int i = 0; i < NTHR / 32; i++) v += ws[i];
        g_part[blockIdx.x] = v;
        __threadfence();
        unsigned int old = atomicAdd(&g_ctr, 1u);
        is_last = (old == NBLK - 1);
    }
    __syncthreads();

    // last-arriving block: deterministic final reduction of 256 partials
    if (is_last && threadIdx.x < 32) {
        volatile float* vp = g_part;
        float v = 0.0f;
#pragma unroll
        for (int i = 0; i < NBLK / 32; i++) v += vp[threadIdx.x + i * 32];
#pragma unroll
        for (int o = 16; o; o >>= 1) v += __shfl_down_sync(0xffffffffu, v, o);
        if (threadIdx.x == 0) {
            out[0] = v;
            g_ctr = 0;   // reset for next graph replay
        }
    }
}

extern "C" void kernel_launch(void* const* d_in, const int* in_sizes, int n_in,
                              void* d_out, int out_size) {
    // metadata order: input(unused), input_ik, input_decoder, target, mean_dqs, std_dqs, offsets
    const float* ik   = (const float*)d_in[1];
    const float* dec  = (const float*)d_in[2];
    const float* tgt  = (const float*)d_in[3];
    const float* mean = (const float*)d_in[4];
    const float* stdv = (const float*)d_in[5];
    const float* offs = (const float*)d_in[6];
    float* out = (float*)d_out;

    fk_loss_kernel<<<NBLK, NTHR>>>(ik, dec, tgt, mean, stdv, offs, out);
}

// round 9
// speedup vs baseline: 1.2373x; 1.1186x over previous
#include <cuda_runtime.h>

#define TT 1024
#define NBLK 256
#define NTHR 256

struct Q { float w, x, y, z; };
struct V3 { float x, y, z; };

__device__ __forceinline__ Q qmul(const Q a, const Q b) {
    return Q{ a.w*b.w - a.x*b.x - a.y*b.y - a.z*b.z,
              a.w*b.x + a.x*b.w + a.y*b.z - a.z*b.y,
              a.w*b.y - a.x*b.z + a.y*b.w + a.z*b.x,
              a.w*b.z + a.x*b.y - a.y*b.x + a.z*b.w };
}
__device__ __forceinline__ Q qconj(const Q q) { return Q{q.w, -q.x, -q.y, -q.z}; }

__device__ __forceinline__ V3 qrot(const Q q, const V3 v) {
    float tx = 2.0f*(q.y*v.z - q.z*v.y);
    float ty = 2.0f*(q.z*v.x - q.x*v.z);
    float tz = 2.0f*(q.x*v.y - q.y*v.x);
    return V3{ v.x + q.w*tx + (q.y*tz - q.z*ty),
               v.y + q.w*ty + (q.z*tx - q.x*tz),
               v.z + q.w*tz + (q.x*ty - q.y*tx) };
}

// ||R(a)-R(b)||_F^2 = 8*(1 - dot(a,b)^2) for unit quats
__device__ __forceinline__ float qdot(const Q a, const Q b) {
    return fmaf(a.w, b.w, fmaf(a.x, b.x, fmaf(a.y, b.y, a.z*b.z)));
}
__device__ __forceinline__ float n2(const V3 a) {
    return fmaf(a.x, a.x, fmaf(a.y, a.y, a.z*a.z));
}

__device__ float g_part[NBLK];
__device__ unsigned int g_ctr = 0;

__global__ void __launch_bounds__(NTHR, 2) fk_loss_kernel(
    const float* __restrict__ ik,   // (64, 168, 1024)
    const float* __restrict__ dec,  // (64, 176, 1024)
    const float* __restrict__ tgt,  // (64, 176, 1024)
    const float* __restrict__ mean, // (176,)
    const float* __restrict__ stdv, // (176,)
    const float* __restrict__ offs, // (22, 3)
    float* __restrict__ out)
{
    __shared__ float smn[176], ssd[176], soff[66];
    for (int i = threadIdx.x; i < 176; i += NTHR) { smn[i] = mean[i]; ssd[i] = stdv[i]; }
    for (int i = threadIdx.x; i < 66; i += NTHR) soff[i] = offs[i];
    __syncthreads();

    int tid = blockIdx.x * NTHR + threadIdx.x;
    int b = tid >> 10, t = tid & 1023;
    const float* ikp = ik  + (size_t)b * 168 * TT + t;
    const float* dcp = dec + (size_t)b * 176 * TT + t;
    const float* tgp = tgt + (size_t)b * 176 * TT + t;

    // -------- software-pipelined raw load buffers (3-deep) --------
    float bA[12], bB[12], bC[12];

    // raw loads for an NS joint: 3 quats (ik, dec, tgt)
#define LD_NS(B, j) do {                                                       \
    B[0]  = ikp[(((j)-1)*8+0)*TT]; B[1]  = ikp[(((j)-1)*8+1)*TT];              \
    B[2]  = ikp[(((j)-1)*8+2)*TT]; B[3]  = ikp[(((j)-1)*8+3)*TT];              \
    B[4]  = dcp[((j)*8+0)*TT];     B[5]  = dcp[((j)*8+1)*TT];                  \
    B[6]  = dcp[((j)*8+2)*TT];     B[7]  = dcp[((j)*8+3)*TT];                  \
    B[8]  = tgp[((j)*8+0)*TT];     B[9]  = tgp[((j)*8+1)*TT];                  \
    B[10] = tgp[((j)*8+2)*TT];     B[11] = tgp[((j)*8+3)*TT];                  \
} while (0)

    // raw loads for an EE joint: 2 quats (ik, tgt) -- dec never needed at leaves
#define LD_EE(B, j) do {                                                       \
    B[0]  = ikp[(((j)-1)*8+0)*TT]; B[1]  = ikp[(((j)-1)*8+1)*TT];              \
    B[2]  = ikp[(((j)-1)*8+2)*TT]; B[3]  = ikp[(((j)-1)*8+3)*TT];              \
    B[8]  = tgp[((j)*8+0)*TT];     B[9]  = tgp[((j)*8+1)*TT];                  \
    B[10] = tgp[((j)*8+2)*TT];     B[11] = tgp[((j)*8+3)*TT];                  \
} while (0)

    // denorm + normalize from a raw buffer slot
#define MKQ(B, o, mc) mkq(&B[o], smn, ssd, mc)

    // root-of-target quat: load + normalize first so it's ready for all steps
    float w0 = fmaf(tgp[0*TT], ssd[0], smn[0]);
    float x0 = fmaf(tgp[1*TT], ssd[1], smn[1]);
    float y0 = fmaf(tgp[2*TT], ssd[2], smn[2]);
    float z0 = fmaf(tgp[3*TT], ssd[3], smn[3]);
    {
        float inv = rsqrtf(fmaf(w0, w0, fmaf(x0, x0, fmaf(y0, y0, z0*z0))));
        w0 *= inv; x0 *= -inv; y0 *= -inv; z0 *= -inv;  // conj folded in
    }
    Q qc0 = Q{w0, x0, y0, z0};

    Q  gI[22], gD[22], gT[22];
    V3 dDI[22], dIT[22];   // pD - pI, pI - pT
    float aep = 0.0f, aer = 0.0f, anp = 0.0f, anr = 0.0f;

    struct MK {
        __device__ static Q mk(const float* r, const float* mn, const float* sd, int mc) {
            float w = fmaf(r[0], sd[mc+0], mn[mc+0]);
            float x = fmaf(r[1], sd[mc+1], mn[mc+1]);
            float y = fmaf(r[2], sd[mc+2], mn[mc+2]);
            float z = fmaf(r[3], sd[mc+3], mn[mc+3]);
            float inv = rsqrtf(fmaf(w, w, fmaf(x, x, fmaf(y, y, z*z))));
            return Q{w*inv, x*inv, y*inv, z*inv};
        }
    };
#define mkq(r, mn, sd, mc) MK::mk(r, mn, sd, mc)

    // NS step consuming a prefetched buffer (telescoped globals: rots[j]=conj(qr0)*qr_j;
    // ik/dec roots are identity so their globals are the raw joint quats)
#define STEP_NS(B, j, p) do {                                                  \
    Q qi = MKQ(B, 0, (j)*8);                                                   \
    Q qd = MKQ(B, 4, (j)*8);                                                   \
    Q qt = MKQ(B, 8, (j)*8);                                                   \
    gI[j] = qi; gD[j] = qd; gT[j] = qmul(qc0, qt);                             \
    if ((p) == 0) {                                                            \
        dDI[j] = V3{0.f,0.f,0.f}; dIT[j] = V3{0.f,0.f,0.f};                    \
    } else {                                                                   \
        V3 off = V3{soff[3*(j)], soff[3*(j)+1], soff[3*(j)+2]};                \
        V3 rI = qrot(gI[p], off);                                              \
        V3 rD = qrot(gD[p], off);                                              \
        V3 rT = qrot(gT[p], off);                                              \
        dDI[j] = V3{dDI[p].x + rD.x - rI.x, dDI[p].y + rD.y - rI.y,            \
                    dDI[p].z + rD.z - rI.z};                                   \
        dIT[j] = V3{dIT[p].x + rI.x - rT.x, dIT[p].y + rI.y - rT.y,            \
                    dIT[p].z + rI.z - rT.z};                                   \
        anp += n2(dDI[j]);                                                     \
    }                                                                          \
    { float d = qdot(qd, qi); anr += fmaf(-d, d, 1.0f); }                      \
} while (0)

#define STEP_EE(B, j, p) do {                                                  \
    Q qi = MKQ(B, 0, (j)*8);                                                   \
    Q qt = MKQ(B, 8, (j)*8);                                                   \
    Q gt = qmul(qc0, qt);                                                      \
    V3 off = V3{soff[3*(j)], soff[3*(j)+1], soff[3*(j)+2]};                    \
    V3 rI = qrot(gI[p], off);                                                  \
    V3 rT = qrot(gT[p], off);                                                  \
    V3 d = V3{dIT[p].x + rI.x - rT.x, dIT[p].y + rI.y - rT.y,                  \
              dIT[p].z + rI.z - rT.z};                                         \
    aep += n2(d);                                                              \
    { float dd = qdot(qi, gt); aer += fmaf(-dd, dd, 1.0f); }                   \
} while (0)

    // ---- pipelined schedule: loads run 2-3 joints ahead of compute ----
    LD_NS(bA, 1); LD_NS(bB, 2); LD_NS(bC, 3);
    STEP_NS(bA, 1, 0);  LD_EE(bA, 4);
    STEP_NS(bB, 2, 1);  LD_NS(bB, 5);
    STEP_NS(bC, 3, 2);  LD_NS(bC, 6);
    STEP_EE(bA, 4, 3);  LD_NS(bA, 7);
    STEP_NS(bB, 5, 0);  LD_EE(bB, 8);
    STEP_NS(bC, 6, 5);  LD_NS(bC, 9);
    STEP_NS(bA, 7, 6);  LD_NS(bA, 10);
    STEP_EE(bB, 8, 7);  LD_NS(bB, 11);
    STEP_NS(bC, 9, 0);  LD_NS(bC, 12);
    STEP_NS(bA, 10, 9); LD_EE(bA, 13);
    STEP_NS(bB, 11, 10); LD_NS(bB, 14);
    STEP_NS(bC, 12, 11); LD_NS(bC, 15);
    STEP_EE(bA, 13, 12); LD_NS(bA, 16);
    STEP_NS(bB, 14, 11); LD_EE(bB, 17);
    STEP_NS(bC, 15, 14); LD_NS(bC, 18);
    STEP_NS(bA, 16, 15); LD_NS(bA, 19);
    STEP_EE(bB, 17, 16); LD_NS(bB, 20);
    STEP_NS(bC, 18, 11); LD_EE(bC, 21);
    STEP_NS(bA, 19, 18);
    STEP_NS(bB, 20, 19);
    STEP_EE(bC, 21, 20);

#undef STEP_NS
#undef STEP_EE
#undef LD_NS
#undef LD_EE
#undef MKQ
#undef mkq

    const float NBT = 65536.0f;
    float s = aep * (1.0f / (NBT * 15.0f))
            + aer * (8.0f / (NBT * 45.0f))
            + anp * (0.1f / (NBT * 48.0f))
            + anr * (0.8f / (NBT * 144.0f));

    // block reduction -> deterministic per-block partial
#pragma unroll
    for (int o = 16; o; o >>= 1) s += __shfl_down_sync(0xffffffffu, s, o);
    __shared__ float ws[NTHR / 32];
    __shared__ bool is_last;
    if ((threadIdx.x & 31) == 0) ws[threadIdx.x >> 5] = s;
    __syncthreads();
    if (threadIdx.x == 0) {
        float v = 0.0f;
#pragma unroll
        for (int i = 0; i < NTHR / 32; i++) v += ws[i];
        g_part[blockIdx.x] = v;
        __threadfence();
        unsigned int old = atomicAdd(&g_ctr, 1u);
        is_last = (old == NBLK - 1);
    }
    __syncthreads();

    // last-arriving block: deterministic final reduction of 256 partials
    if (is_last && threadIdx.x < 32) {
        volatile float* vp = g_part;
        float v = 0.0f;
#pragma unroll
        for (int i = 0; i < NBLK / 32; i++) v += vp[threadIdx.x + i * 32];
#pragma unroll
        for (int o = 16; o; o >>= 1) v += __shfl_down_sync(0xffffffffu, v, o);
        if (threadIdx.x == 0) {
            out[0] = v;
            g_ctr = 0;   // reset for next graph replay
        }
    }
}

extern "C" void kernel_launch(void* const* d_in, const int* in_sizes, int n_in,
                              void* d_out, int out_size) {
    // metadata order: input(unused), input_ik, input_decoder, target, mean_dqs, std_dqs, offsets
    const float* ik   = (const float*)d_in[1];
    const float* dec  = (const float*)d_in[2];
    const float* tgt  = (const float*)d_in[3];
    const float* mean = (const float*)d_in[4];
    const float* stdv = (const float*)d_in[5];
    const float* offs = (const float*)d_in[6];
    float* out = (float*)d_out;

    fk_loss_kernel<<<NBLK, NTHR>>>(ik, dec, tgt, mean, stdv, offs, out);
}